// round 2
// baseline (speedup 1.0000x reference)
#include <cuda_runtime.h>
#include <cstdint>

// Problem constants
#define B_      2048
#define N_      64
#define OBS_    8
#define PRED_   12
#define IN_     6
#define E_      512
#define C_      6
#define CN_     7          // C + 1
#define K_      20
#define DSELF_  120        // IN*(OBS+PRED)
#define DNEI_   48         // IN*OBS
#define RTOT_   (B_ * N_)  // 131072
#define EPSF    1e-4f

#define X_ELEMS ((size_t)B_ * K_ * E_)   // 20,971,520

// ---------------- scratch (__device__ globals; no allocation) ----------------
__device__ int   g_perm[RTOT_];                  // packed-pos -> original row
__device__ int   g_cnt[CN_];
__device__ int   g_off[CN_];
__device__ int   g_cur[CN_];
__device__ float g_anchor[(size_t)C_ * K_ * E_]; // 245 KB

// ---------------- kernel 0: reset counters ----------------
__global__ void k_init() {
    int t = threadIdx.x;
    if (t < CN_) { g_cnt[t] = 0; }
}

// ---------------- kernel 1: per-class row counts ----------------
__global__ void k_count(const int* __restrict__ nei_labels) {
    __shared__ int sc[CN_];
    if (threadIdx.x < CN_) sc[threadIdx.x] = 0;
    __syncthreads();
    int i = blockIdx.x * blockDim.x + threadIdx.x;
    if (i < RTOT_) atomicAdd(&sc[nei_labels[i]], 1);
    __syncthreads();
    if (threadIdx.x < CN_ && sc[threadIdx.x] > 0)
        atomicAdd(&g_cnt[threadIdx.x], sc[threadIdx.x]);
}

// ---------------- kernel 2: exclusive prefix over 7 classes ----------------
__global__ void k_prefix() {
    if (threadIdx.x == 0 && blockIdx.x == 0) {
        int acc = 0;
        for (int c = 0; c < CN_; c++) {
            g_off[c] = acc;
            g_cur[c] = acc;
            acc += g_cnt[c];
        }
    }
}

// ---------------- kernel 3: index-only scatter into class bins ----------------
// (no data movement — GEMM gathers rows of `neis` directly via g_perm)
__global__ void k_scatter_idx(const int* __restrict__ nei_labels) {
    int i = blockIdx.x * blockDim.x + threadIdx.x;
    if (i >= RTOT_) return;
    int c = nei_labels[i];
    int pos = atomicAdd(&g_cur[c], 1);
    g_perm[pos] = i;
}

// ---------------- kernel 4: grouped GEMM  out[row] = f(neis[row]) @ W_nei[c] + b_nei[c] --
// Tiles: 128 rows x 128 cols, K = 48 (single smem stage).
// 256 threads, each computes an 8x8 register tile.
// A rows gathered from `neis` via g_perm; signed-reciprocal applied in the load.
#define MT 128
#define NT 128
#define GEMM_MAX_MTILES ((RTOT_ / MT) + CN_)   // 1024 + 7
#define GEMM_GRID (GEMM_MAX_MTILES * (E_ / NT))

__global__ __launch_bounds__(256, 2)
void k_gemm(const float* __restrict__ neis,
            const float* __restrict__ W_nei,
            const float* __restrict__ b_nei,
            float*       __restrict__ out_nei) {
    // ---- block -> (class, m-tile, n-tile) mapping from device-side counts ----
    int nt  = blockIdx.x & 3;         // E_/NT = 4
    int mid = blockIdx.x >> 2;
    int c = -1, mt = 0, acc_t = 0;
#pragma unroll
    for (int cc = 0; cc < CN_; cc++) {
        int t = (g_cnt[cc] + MT - 1) >> 7;
        if (c < 0 && mid < acc_t + t) { c = cc; mt = mid - acc_t; }
        acc_t += t;
    }
    if (c < 0) return;

    int cnt = g_cnt[c];
    int off = g_off[c];
    int m0  = mt * MT;

    __shared__ float As[DNEI_][MT];   // 24 KB, A transposed for coalesced compute reads
    __shared__ float Bs[DNEI_][NT];   // 24 KB
    __shared__ int   s_perm[MT];

    int tid = threadIdx.x;

    // stage the permutation slice for this m-tile
    if (tid < MT) {
        int r = m0 + tid;
        s_perm[tid] = (r < cnt) ? g_perm[off + r] : -1;
    }
    __syncthreads();

    // gather A tile from neis (+ signed-reciprocal transform):
    // 128 rows x 12 float4 = 1536 float4, 6 per thread.
    // 12 consecutive threads read one row's contiguous 192 B — coalesced.
#pragma unroll
    for (int it = 0; it < 6; it++) {
        int idx = tid + it * 256;
        int r = idx / 12, q = idx % 12;
        int rg = s_perm[r];
        float4 v = make_float4(0.f, 0.f, 0.f, 0.f);
        if (rg >= 0) {
            v = *(const float4*)(neis + (size_t)rg * DNEI_ + q * 4);
            v.x = (v.x >= 0.f) ? 1.f / (v.x + EPSF) : 1.f / (v.x - EPSF);
            v.y = (v.y >= 0.f) ? 1.f / (v.y + EPSF) : 1.f / (v.y - EPSF);
            v.z = (v.z >= 0.f) ? 1.f / (v.z + EPSF) : 1.f / (v.z - EPSF);
            v.w = (v.w >= 0.f) ? 1.f / (v.w + EPSF) : 1.f / (v.w - EPSF);
        }
        As[q * 4 + 0][r] = v.x;
        As[q * 4 + 1][r] = v.y;
        As[q * 4 + 2][r] = v.z;
        As[q * 4 + 3][r] = v.w;
    }
    // load B tile: W_nei[c][k][nt*128 + col], 48 x 32 float4 = 1536 float4
    const float* Wc = W_nei + (size_t)c * DNEI_ * E_ + nt * NT;
#pragma unroll
    for (int it = 0; it < 6; it++) {
        int idx = tid + it * 256;
        int k = idx / 32, q = idx % 32;
        float4 v = *(const float4*)(Wc + (size_t)k * E_ + q * 4);
        *(float4*)(&Bs[k][q * 4]) = v;
    }
    __syncthreads();

    int tcol = tid & 15;        // 16 col-threads  -> 8 cols each
    int trow = tid >> 4;        // 16 row-threads  -> 8 rows each

    float acc[8][8];
#pragma unroll
    for (int i = 0; i < 8; i++)
#pragma unroll
        for (int j = 0; j < 8; j++) acc[i][j] = 0.f;

#pragma unroll 4
    for (int k = 0; k < DNEI_; k++) {
        float a[8], b[8];
        *(float4*)(a)     = *(const float4*)(&As[k][trow * 8]);
        *(float4*)(a + 4) = *(const float4*)(&As[k][trow * 8 + 4]);
        *(float4*)(b)     = *(const float4*)(&Bs[k][tcol * 8]);
        *(float4*)(b + 4) = *(const float4*)(&Bs[k][tcol * 8 + 4]);
#pragma unroll
        for (int i = 0; i < 8; i++)
#pragma unroll
            for (int j = 0; j < 8; j++)
                acc[i][j] += a[i] * b[j];
    }

    // epilogue: add bias, scatter rows back via perm
    const float* bias = b_nei + (size_t)c * E_ + nt * NT + tcol * 8;
    float bv[8];
    *(float4*)(bv)     = *(const float4*)(bias);
    *(float4*)(bv + 4) = *(const float4*)(bias + 4);

#pragma unroll
    for (int i = 0; i < 8; i++) {
        int r  = trow * 8 + i;
        int rg = s_perm[r];
        if (rg >= 0) {
            float* o = out_nei + (size_t)rg * E_ + nt * NT + tcol * 8;
            float4 v0 = make_float4(acc[i][0] + bv[0], acc[i][1] + bv[1],
                                    acc[i][2] + bv[2], acc[i][3] + bv[3]);
            float4 v1 = make_float4(acc[i][4] + bv[4], acc[i][5] + bv[5],
                                    acc[i][6] + bv[6], acc[i][7] + bv[7]);
            *(float4*)(o)     = v0;
            *(float4*)(o + 4) = v1;
        }
    }
}

// ---------------- kernel 5: anchor_part[c,k,:] = it[c,k] @ W_self[c][48:] + b_self[c] ----
__global__ void k_anchor(const float* __restrict__ init_trajs,
                         const float* __restrict__ W_self,
                         const float* __restrict__ b_self) {
    int c  = blockIdx.x / K_;
    int kk = blockIdx.x % K_;
    __shared__ float tr[PRED_ * IN_];   // 72
    if (threadIdx.x < PRED_ * IN_)
        tr[threadIdx.x] = init_trajs[((size_t)c * K_ + kk) * (PRED_ * IN_) + threadIdx.x];
    __syncthreads();

    int col = threadIdx.x * 4;          // 128 threads x 4 cols = 512
    const float* bb = b_self + (size_t)c * E_ + col;
    float4 acc = *(const float4*)bb;
    const float* W = W_self + ((size_t)c * DSELF_ + DNEI_) * E_ + col;
#pragma unroll 8
    for (int j = 0; j < PRED_ * IN_; j++) {
        float  t = tr[j];
        float4 w = *(const float4*)(W + (size_t)j * E_);
        acc.x += t * w.x; acc.y += t * w.y; acc.z += t * w.z; acc.w += t * w.w;
    }
    *(float4*)(g_anchor + ((size_t)c * K_ + kk) * E_ + col) = acc;
}

// ---------------- kernel 6: x[b,k,:] = obs[b] @ W_self[c][:48] + anchor[c,k,:] ----------
__global__ void k_x(const float* __restrict__ obs,
                    const float* __restrict__ W_self,
                    const int*   __restrict__ self_labels,
                    float*       __restrict__ out_x) {
    int b = blockIdx.x;
    __shared__ float ob[DNEI_];
    if (threadIdx.x < DNEI_)
        ob[threadIdx.x] = obs[(size_t)b * DNEI_ + threadIdx.x];
    __syncthreads();

    int c   = self_labels[b];
    int col = threadIdx.x * 4;          // 128 threads x 4 cols
    const float* W = W_self + (size_t)c * DSELF_ * E_ + col;
    float4 acc = make_float4(0.f, 0.f, 0.f, 0.f);
#pragma unroll 8
    for (int j = 0; j < DNEI_; j++) {
        float  t = ob[j];
        float4 w = *(const float4*)(W + (size_t)j * E_);
        acc.x += t * w.x; acc.y += t * w.y; acc.z += t * w.z; acc.w += t * w.w;
    }
#pragma unroll
    for (int kk = 0; kk < K_; kk++) {
        float4 an = *(const float4*)(g_anchor + ((size_t)c * K_ + kk) * E_ + col);
        float4 v  = make_float4(acc.x + an.x, acc.y + an.y, acc.z + an.z, acc.w + an.w);
        *(float4*)(out_x + ((size_t)b * K_ + kk) * E_ + col) = v;
    }
}

// ---------------- launcher ----------------
extern "C" void kernel_launch(void* const* d_in, const int* in_sizes, int n_in,
                              void* d_out, int out_size) {
    const float* obs         = (const float*)d_in[0];
    const float* neis        = (const float*)d_in[1];
    const float* init_trajs  = (const float*)d_in[2];
    const float* W_self      = (const float*)d_in[3];
    const float* b_self      = (const float*)d_in[4];
    const float* W_nei       = (const float*)d_in[5];
    const float* b_nei       = (const float*)d_in[6];
    const int*   self_labels = (const int*)d_in[7];
    const int*   nei_labels  = (const int*)d_in[8];

    float* out_x   = (float*)d_out;
    float* out_nei = (float*)d_out + X_ELEMS;

    // nei_feats path
    k_init<<<1, 32>>>();
    k_count<<<(RTOT_ + 255) / 256, 256>>>(nei_labels);
    k_prefix<<<1, 32>>>();
    k_scatter_idx<<<(RTOT_ + 255) / 256, 256>>>(nei_labels);
    k_gemm<<<GEMM_GRID, 256>>>(neis, W_nei, b_nei, out_nei);

    // x path
    k_anchor<<<C_ * K_, 128>>>(init_trajs, W_self, b_self);
    k_x<<<B_, 128>>>(obs, W_self, self_labels, out_x);
}

// round 3
// speedup vs baseline: 1.2263x; 1.2263x over previous
#include <cuda_runtime.h>
#include <cstdint>

typedef unsigned long long u64;

// Problem constants
#define B_      2048
#define N_      64
#define OBS_    8
#define PRED_   12
#define IN_     6
#define E_      512
#define C_      6
#define CN_     7          // C + 1
#define K_      20
#define DSELF_  120        // IN*(OBS+PRED)
#define DNEI_   48         // IN*OBS
#define RTOT_   (B_ * N_)  // 131072
#define NBLK_   (RTOT_ / 256)   // 512
#define EPSF    1e-4f

#define X_ELEMS ((size_t)B_ * K_ * E_)   // 20,971,520

// ---------------- scratch (__device__ globals; no allocation) ----------------
__device__ float g_A[(size_t)RTOT_ * DNEI_];     // packed transformed features (~25 MB)
__device__ int   g_perm[RTOT_];                  // packed-pos -> original row
__device__ int   g_bcnt[CN_][NBLK_];             // per-block class counts
__device__ int   g_base[CN_][NBLK_];             // per-class excl prefix over blocks
__device__ int   g_cnt[CN_];
__device__ int   g_off[CN_];
__device__ float g_anchor[(size_t)C_ * K_ * E_]; // 245 KB

// ---------------- kernel 1: per-block class histograms ----------------
__global__ void k_count(const int* __restrict__ nei_labels) {
    __shared__ int sc[CN_];
    if (threadIdx.x < CN_) sc[threadIdx.x] = 0;
    __syncthreads();
    int i = blockIdx.x * 256 + threadIdx.x;   // RTOT_ % 256 == 0
    atomicAdd(&sc[nei_labels[i]], 1);
    __syncthreads();
    if (threadIdx.x < CN_) g_bcnt[threadIdx.x][blockIdx.x] = sc[threadIdx.x];
}

// ---------------- kernel 2: per-class scan over blocks + class offsets --------
// 7 warps, warp w scans class w's 512 block counts via shuffle scan.
__global__ void k_prefix() {
    int w    = threadIdx.x >> 5;
    int lane = threadIdx.x & 31;
    __shared__ int tot[CN_];
    if (w < CN_) {
        int acc = 0;
#pragma unroll
        for (int seg = 0; seg < NBLK_ / 32; seg++) {
            int v = g_bcnt[w][seg * 32 + lane];
            int s = v;
#pragma unroll
            for (int d = 1; d < 32; d <<= 1) {
                int t = __shfl_up_sync(0xffffffffu, s, d);
                if (lane >= d) s += t;
            }
            g_base[w][seg * 32 + lane] = acc + s - v;   // exclusive within class
            acc += __shfl_sync(0xffffffffu, s, 31);
        }
        if (lane == 0) tot[w] = acc;
    }
    __syncthreads();
    if (threadIdx.x == 0) {
        int a = 0;
        for (int c = 0; c < CN_; c++) { g_off[c] = a; g_cnt[c] = tot[c]; a += tot[c]; }
    }
}

// ---------------- kernel 3: deterministic scatter + transform + packed copy ----
__global__ void k_scattercopy(const float* __restrict__ neis,
                              const int*   __restrict__ nei_labels) {
    __shared__ int s_cur[CN_];
    __shared__ int s_pos[256];
    int tid = threadIdx.x;
    int blk = blockIdx.x;
    if (tid < CN_) s_cur[tid] = g_off[tid] + g_base[tid][blk];
    __syncthreads();

    int row = blk * 256 + tid;
    int c   = nei_labels[row];
    int pos = atomicAdd(&s_cur[c], 1);   // smem atomic: 7 addrs, ~fast
    s_pos[tid]  = pos;
    g_perm[pos] = row;
    __syncthreads();

    // copy 256 rows x 12 float4; 12 consecutive threads per row (coalesced reads),
    // same-class rows land in contiguous packed chunks (coalesced-ish writes).
#pragma unroll
    for (int it = 0; it < 12; it++) {
        int idx = it * 256 + tid;
        int r = idx / 12, q = idx % 12;
        float4 v = *(const float4*)(neis + ((size_t)blk * 256 + r) * DNEI_ + q * 4);
        v.x = (v.x >= 0.f) ? 1.f / (v.x + EPSF) : 1.f / (v.x - EPSF);
        v.y = (v.y >= 0.f) ? 1.f / (v.y + EPSF) : 1.f / (v.y - EPSF);
        v.z = (v.z >= 0.f) ? 1.f / (v.z + EPSF) : 1.f / (v.z - EPSF);
        v.w = (v.w >= 0.f) ? 1.f / (v.w + EPSF) : 1.f / (v.w - EPSF);
        *(float4*)(g_A + (size_t)s_pos[r] * DNEI_ + q * 4) = v;
    }
}

// ---------------- f32x2 helpers ----------------
__device__ __forceinline__ u64 pack_dup(float a) {
    u64 r;
    unsigned int ai = __float_as_uint(a);
    asm("mov.b64 %0, {%1, %1};" : "=l"(r) : "r"(ai));
    return r;
}
__device__ __forceinline__ void fma2(u64& acc, u64 a, u64 b) {
    asm("fma.rn.f32x2 %0, %1, %2, %3;" : "=l"(acc) : "l"(a), "l"(b), "l"(acc));
}
__device__ __forceinline__ float2 unpack2(u64 v) {
    unsigned int lo, hi;
    asm("mov.b64 {%0, %1}, %2;" : "=r"(lo), "=r"(hi) : "l"(v));
    return make_float2(__uint_as_float(lo), __uint_as_float(hi));
}

// ---------------- kernel 4: grouped GEMM, FFMA2 inner loop ----------------
// Tiles: 128x128, K=48 single stage, 256 threads, 8x8 per thread (as 8x4 f32x2).
#define MT 128
#define NT 128
#define GEMM_MAX_MTILES ((RTOT_ / MT) + CN_)   // 1024 + 7
#define GEMM_GRID (GEMM_MAX_MTILES * (E_ / NT))

__global__ __launch_bounds__(256, 2)
void k_gemm(const float* __restrict__ W_nei,
            const float* __restrict__ b_nei,
            float*       __restrict__ out_nei) {
    int nt  = blockIdx.x & 3;         // E_/NT = 4
    int mid = blockIdx.x >> 2;
    int c = -1, mt = 0, acc_t = 0;
#pragma unroll
    for (int cc = 0; cc < CN_; cc++) {
        int t = (g_cnt[cc] + MT - 1) >> 7;
        if (c < 0 && mid < acc_t + t) { c = cc; mt = mid - acc_t; }
        acc_t += t;
    }
    if (c < 0) return;

    int cnt = g_cnt[c];
    int off = g_off[c];
    int m0  = mt * MT;

    __shared__ float As[DNEI_][MT];   // 24 KB (A transposed)
    __shared__ float Bs[DNEI_][NT];   // 24 KB

    int tid = threadIdx.x;

    // load A tile (packed, contiguous): 128 rows x 12 float4, 6 per thread
#pragma unroll
    for (int it = 0; it < 6; it++) {
        int idx = tid + it * 256;
        int r = idx / 12, q = idx % 12;
        float4 v = make_float4(0.f, 0.f, 0.f, 0.f);
        if (m0 + r < cnt)
            v = *(const float4*)(g_A + (size_t)(off + m0 + r) * DNEI_ + q * 4);
        As[q * 4 + 0][r] = v.x;
        As[q * 4 + 1][r] = v.y;
        As[q * 4 + 2][r] = v.z;
        As[q * 4 + 3][r] = v.w;
    }
    // load B tile: 48 x 32 float4
    const float* Wc = W_nei + (size_t)c * DNEI_ * E_ + nt * NT;
#pragma unroll
    for (int it = 0; it < 6; it++) {
        int idx = tid + it * 256;
        int k = idx / 32, q = idx % 32;
        float4 v = *(const float4*)(Wc + (size_t)k * E_ + q * 4);
        *(float4*)(&Bs[k][q * 4]) = v;
    }
    __syncthreads();

    int tcol = tid & 15;        // 16 col-threads -> 8 cols each (4 f32x2 pairs)
    int trow = tid >> 4;        // 16 row-threads -> 8 rows each

    u64 acc2[8][4];
#pragma unroll
    for (int i = 0; i < 8; i++)
#pragma unroll
        for (int j = 0; j < 4; j++) acc2[i][j] = 0ull;

#pragma unroll 4
    for (int k = 0; k < DNEI_; k++) {
        float a[8];
        *(float4*)(a)     = *(const float4*)(&As[k][trow * 8]);
        *(float4*)(a + 4) = *(const float4*)(&As[k][trow * 8 + 4]);
        // b pairs come free: reinterpret LDS.128 as 2x f32x2
        ulonglong2 bb0 = *(const ulonglong2*)(&Bs[k][tcol * 8]);
        ulonglong2 bb1 = *(const ulonglong2*)(&Bs[k][tcol * 8 + 4]);
        u64 b2[4] = { bb0.x, bb0.y, bb1.x, bb1.y };
        u64 a2[8];
#pragma unroll
        for (int i = 0; i < 8; i++) a2[i] = pack_dup(a[i]);
#pragma unroll
        for (int i = 0; i < 8; i++)
#pragma unroll
            for (int j = 0; j < 4; j++)
                fma2(acc2[i][j], a2[i], b2[j]);
    }

    // epilogue: bias + scatter back via perm
    const float* bias = b_nei + (size_t)c * E_ + nt * NT + tcol * 8;
    float bv[8];
    *(float4*)(bv)     = *(const float4*)(bias);
    *(float4*)(bv + 4) = *(const float4*)(bias + 4);

#pragma unroll
    for (int i = 0; i < 8; i++) {
        int r = m0 + trow * 8 + i;
        if (r < cnt) {
            int rg = g_perm[off + r];
            float* o = out_nei + (size_t)rg * E_ + nt * NT + tcol * 8;
            float2 p0 = unpack2(acc2[i][0]);
            float2 p1 = unpack2(acc2[i][1]);
            float2 p2 = unpack2(acc2[i][2]);
            float2 p3 = unpack2(acc2[i][3]);
            float4 v0 = make_float4(p0.x + bv[0], p0.y + bv[1],
                                    p1.x + bv[2], p1.y + bv[3]);
            float4 v1 = make_float4(p2.x + bv[4], p2.y + bv[5],
                                    p3.x + bv[6], p3.y + bv[7]);
            *(float4*)(o)     = v0;
            *(float4*)(o + 4) = v1;
        }
    }
}

// ---------------- kernel 5: anchor_part[c,k,:] = it[c,k] @ W_self[c][48:] + b_self[c] ----
__global__ void k_anchor(const float* __restrict__ init_trajs,
                         const float* __restrict__ W_self,
                         const float* __restrict__ b_self) {
    int c  = blockIdx.x / K_;
    int kk = blockIdx.x % K_;
    __shared__ float tr[PRED_ * IN_];   // 72
    if (threadIdx.x < PRED_ * IN_)
        tr[threadIdx.x] = init_trajs[((size_t)c * K_ + kk) * (PRED_ * IN_) + threadIdx.x];
    __syncthreads();

    int col = threadIdx.x * 4;          // 128 threads x 4 cols = 512
    const float* bb = b_self + (size_t)c * E_ + col;
    float4 acc = *(const float4*)bb;
    const float* W = W_self + ((size_t)c * DSELF_ + DNEI_) * E_ + col;
#pragma unroll 8
    for (int j = 0; j < PRED_ * IN_; j++) {
        float  t = tr[j];
        float4 w = *(const float4*)(W + (size_t)j * E_);
        acc.x += t * w.x; acc.y += t * w.y; acc.z += t * w.z; acc.w += t * w.w;
    }
    *(float4*)(g_anchor + ((size_t)c * K_ + kk) * E_ + col) = acc;
}

// ---------------- kernel 6: x[b,k,:] = obs[b] @ W_self[c][:48] + anchor[c,k,:] ----------
__global__ void k_x(const float* __restrict__ obs,
                    const float* __restrict__ W_self,
                    const int*   __restrict__ self_labels,
                    float*       __restrict__ out_x) {
    int b = blockIdx.x;
    __shared__ float ob[DNEI_];
    if (threadIdx.x < DNEI_)
        ob[threadIdx.x] = obs[(size_t)b * DNEI_ + threadIdx.x];
    __syncthreads();

    int c   = self_labels[b];
    int col = threadIdx.x * 4;          // 128 threads x 4 cols
    const float* W = W_self + (size_t)c * DSELF_ * E_ + col;
    float4 acc = make_float4(0.f, 0.f, 0.f, 0.f);
#pragma unroll 8
    for (int j = 0; j < DNEI_; j++) {
        float  t = ob[j];
        float4 w = *(const float4*)(W + (size_t)j * E_);
        acc.x += t * w.x; acc.y += t * w.y; acc.z += t * w.z; acc.w += t * w.w;
    }
#pragma unroll
    for (int kk = 0; kk < K_; kk++) {
        float4 an = *(const float4*)(g_anchor + ((size_t)c * K_ + kk) * E_ + col);
        float4 v  = make_float4(acc.x + an.x, acc.y + an.y, acc.z + an.z, acc.w + an.w);
        *(float4*)(out_x + ((size_t)b * K_ + kk) * E_ + col) = v;
    }
}

// ---------------- launcher ----------------
extern "C" void kernel_launch(void* const* d_in, const int* in_sizes, int n_in,
                              void* d_out, int out_size) {
    const float* obs         = (const float*)d_in[0];
    const float* neis        = (const float*)d_in[1];
    const float* init_trajs  = (const float*)d_in[2];
    const float* W_self      = (const float*)d_in[3];
    const float* b_self      = (const float*)d_in[4];
    const float* W_nei       = (const float*)d_in[5];
    const float* b_nei       = (const float*)d_in[6];
    const int*   self_labels = (const int*)d_in[7];
    const int*   nei_labels  = (const int*)d_in[8];

    float* out_x   = (float*)d_out;
    float* out_nei = (float*)d_out + X_ELEMS;

    // nei_feats path (deterministic two-pass binning, no global atomics)
    k_count<<<NBLK_, 256>>>(nei_labels);
    k_prefix<<<1, 256>>>();
    k_scattercopy<<<NBLK_, 256>>>(neis, nei_labels);
    k_gemm<<<GEMM_GRID, 256>>>(W_nei, b_nei, out_nei);

    // x path
    k_anchor<<<C_ * K_, 128>>>(init_trajs, W_self, b_self);
    k_x<<<B_, 128>>>(obs, W_self, self_labels, out_x);
}

// round 5
// speedup vs baseline: 1.3746x; 1.1209x over previous
#include <cuda_runtime.h>
#include <cuda_bf16.h>
#include <cstdint>

typedef unsigned long long u64;

// Problem constants
#define B_      2048
#define N_      64
#define OBS_    8
#define PRED_   12
#define IN_     6
#define E_      512
#define C_      6
#define CN_     7          // C + 1
#define K_      20
#define DSELF_  120        // IN*(OBS+PRED)
#define DNEI_   48         // IN*OBS
#define RTOT_   (B_ * N_)  // 131072
#define NBLK_   (RTOT_ / 256)   // 512
#define EPSF    1e-4f

#define KP_     144        // split-K: [hi(48) | lo(48) | hi(48)]
#define ROWB_   (KP_ * 2)  // 288 bytes per packed row
#define X_ELEMS ((size_t)B_ * K_ * E_)   // 20,971,520

// ---------------- scratch (__device__ globals; no allocation) ----------------
__device__ __nv_bfloat16 g_Ab[(size_t)RTOT_ * KP_];      // packed split-A rows (~38 MB)
__device__ __nv_bfloat16 g_Wb[(size_t)CN_ * E_ * KP_];   // split weights (~1 MB)
__device__ int   g_perm[RTOT_];
__device__ int   g_bcnt[CN_][NBLK_];
__device__ int   g_base[CN_][NBLK_];
__device__ int   g_cnt[CN_];
__device__ int   g_off[CN_];
__device__ float g_anchor[(size_t)C_ * K_ * E_];

// ---------------- kernel 1: per-block class histograms ----------------
__global__ void k_count(const int* __restrict__ nei_labels) {
    __shared__ int sc[CN_];
    if (threadIdx.x < CN_) sc[threadIdx.x] = 0;
    __syncthreads();
    int i = blockIdx.x * 256 + threadIdx.x;
    atomicAdd(&sc[nei_labels[i]], 1);
    __syncthreads();
    if (threadIdx.x < CN_) g_bcnt[threadIdx.x][blockIdx.x] = sc[threadIdx.x];
}

// ---------------- kernel 2: per-class scan over blocks ----------------
__global__ void k_prefix() {
    int w    = threadIdx.x >> 5;
    int lane = threadIdx.x & 31;
    __shared__ int tot[CN_];
    if (w < CN_) {
        int acc = 0;
#pragma unroll
        for (int seg = 0; seg < NBLK_ / 32; seg++) {
            int v = g_bcnt[w][seg * 32 + lane];
            int s = v;
#pragma unroll
            for (int d = 1; d < 32; d <<= 1) {
                int t = __shfl_up_sync(0xffffffffu, s, d);
                if (lane >= d) s += t;
            }
            g_base[w][seg * 32 + lane] = acc + s - v;
            acc += __shfl_sync(0xffffffffu, s, 31);
        }
        if (lane == 0) tot[w] = acc;
    }
    __syncthreads();
    if (threadIdx.x == 0) {
        int a = 0;
        for (int c = 0; c < CN_; c++) { g_off[c] = a; g_cnt[c] = tot[c]; a += tot[c]; }
    }
}

// ---------------- kernel 3: scatter + transform + bf16 hi/lo split copy --------
__global__ void k_scattercopy(const float* __restrict__ neis,
                              const int*   __restrict__ nei_labels) {
    __shared__ int s_cur[CN_];
    __shared__ int s_pos[256];
    int tid = threadIdx.x;
    int blk = blockIdx.x;
    if (tid < CN_) s_cur[tid] = g_off[tid] + g_base[tid][blk];
    __syncthreads();

    int row = blk * 256 + tid;
    int c   = nei_labels[row];
    int pos = atomicAdd(&s_cur[c], 1);
    s_pos[tid]  = pos;
    g_perm[pos] = row;
    __syncthreads();

#pragma unroll
    for (int it = 0; it < 12; it++) {
        int idx = it * 256 + tid;
        int r = idx / 12, q = idx % 12;       // q: float4 chunk 0..11
        float4 v = *(const float4*)(neis + ((size_t)blk * 256 + r) * DNEI_ + q * 4);
        v.x = (v.x >= 0.f) ? 1.f / (v.x + EPSF) : 1.f / (v.x - EPSF);
        v.y = (v.y >= 0.f) ? 1.f / (v.y + EPSF) : 1.f / (v.y - EPSF);
        v.z = (v.z >= 0.f) ? 1.f / (v.z + EPSF) : 1.f / (v.z - EPSF);
        v.w = (v.w >= 0.f) ? 1.f / (v.w + EPSF) : 1.f / (v.w - EPSF);

        __nv_bfloat16 hx = __float2bfloat16(v.x), hy = __float2bfloat16(v.y);
        __nv_bfloat16 hz = __float2bfloat16(v.z), hw = __float2bfloat16(v.w);
        __nv_bfloat16 lx = __float2bfloat16(v.x - __bfloat162float(hx));
        __nv_bfloat16 ly = __float2bfloat16(v.y - __bfloat162float(hy));
        __nv_bfloat16 lz = __float2bfloat16(v.z - __bfloat162float(hz));
        __nv_bfloat16 lw = __float2bfloat16(v.w - __bfloat162float(hw));

        uint32_t h01 = ((uint32_t)__bfloat16_as_ushort(hy) << 16) | __bfloat16_as_ushort(hx);
        uint32_t h23 = ((uint32_t)__bfloat16_as_ushort(hw) << 16) | __bfloat16_as_ushort(hz);
        uint32_t l01 = ((uint32_t)__bfloat16_as_ushort(ly) << 16) | __bfloat16_as_ushort(lx);
        uint32_t l23 = ((uint32_t)__bfloat16_as_ushort(lw) << 16) | __bfloat16_as_ushort(lz);

        char* rb = (char*)g_Ab + (size_t)s_pos[r] * ROWB_;
        *(uint2*)(rb + q * 8)        = make_uint2(h01, h23);   // seg0: hi (k 0..47)
        *(uint2*)(rb + 96 + q * 8)   = make_uint2(l01, l23);   // seg1: lo (k 48..95)
        *(uint2*)(rb + 192 + q * 8)  = make_uint2(h01, h23);   // seg2: hi (k 96..143)
    }
}

// ---------------- kernel 3b: split weights [W_hi | W_hi | W_lo] ----------------
__global__ void k_wprep(const float* __restrict__ W_nei) {
    int g = blockIdx.x * 256 + threadIdx.x;      // (c, n)
    if (g >= CN_ * E_) return;
    int c = g / E_, n = g % E_;
    char* rb = (char*)g_Wb + (size_t)g * ROWB_;
    const float* W = W_nei + (size_t)c * DNEI_ * E_ + n;
    for (int k = 0; k < DNEI_; k++) {
        float w = W[(size_t)k * E_];
        __nv_bfloat16 h = __float2bfloat16(w);
        __nv_bfloat16 l = __float2bfloat16(w - __bfloat162float(h));
        *(__nv_bfloat16*)(rb + k * 2)       = h;   // seg0 (pairs A hi)
        *(__nv_bfloat16*)(rb + 96 + k * 2)  = h;   // seg1 (pairs A lo)
        *(__nv_bfloat16*)(rb + 192 + k * 2) = l;   // seg2 (pairs A hi)
    }
}

// ================= mma.sync helpers =================
__device__ __forceinline__ uint32_t smem_u32(const void* p) {
    uint32_t a;
    asm("{ .reg .u64 t; cvta.to.shared.u64 t, %1; cvt.u32.u64 %0, t; }" : "=r"(a) : "l"(p));
    return a;
}
__device__ __forceinline__ void ldsm_x4(uint32_t& r0, uint32_t& r1, uint32_t& r2, uint32_t& r3,
                                        uint32_t addr) {
    asm volatile("ldmatrix.sync.aligned.m8n8.x4.shared.b16 {%0,%1,%2,%3}, [%4];"
                 : "=r"(r0), "=r"(r1), "=r"(r2), "=r"(r3) : "r"(addr));
}
__device__ __forceinline__ void mma16816(float* c, const uint32_t* a, uint32_t b0, uint32_t b1) {
    asm volatile("mma.sync.aligned.m16n8k16.row.col.f32.bf16.bf16.f32 "
                 "{%0,%1,%2,%3}, {%4,%5,%6,%7}, {%8,%9}, {%0,%1,%2,%3};"
                 : "+f"(c[0]), "+f"(c[1]), "+f"(c[2]), "+f"(c[3])
                 : "r"(a[0]), "r"(a[1]), "r"(a[2]), "r"(a[3]), "r"(b0), "r"(b1));
}

// ---------------- kernel 4: grouped GEMM via mma.sync bf16 ----------------
// 128x128 tile, K'=144 resident. 256 threads = 8 warps (2x4), warp = 64x32.
#define MT 128
#define NT 128
#define GEMM_MAX_MTILES ((RTOT_ / MT) + CN_)   // 1031
#define GEMM_GRID (GEMM_MAX_MTILES * (E_ / NT))
#define STRIDE_B 304                           // padded row stride (152 bf16) — LDSM conflict-free
#define TILE_B   (128 * STRIDE_B)              // 38912 bytes
#define SMEM_HDR 1024                          // s_perm(512) + s_bias(512)
#define SMEM_BYTES (SMEM_HDR + 2 * TILE_B)     // 78848

__global__ void __launch_bounds__(256, 2)
k_gemm_mma(const float* __restrict__ b_nei,
           float*       __restrict__ out_nei) {
    int nt  = blockIdx.x & 3;
    int mid = blockIdx.x >> 2;
    int c = -1, mt = 0, acc_t = 0;
#pragma unroll
    for (int cc = 0; cc < CN_; cc++) {
        int t = (g_cnt[cc] + MT - 1) >> 7;
        if (c < 0 && mid < acc_t + t) { c = cc; mt = mid - acc_t; }
        acc_t += t;
    }
    if (c < 0) return;

    int cnt = g_cnt[c];
    int off = g_off[c];
    int m0  = mt * MT;

    extern __shared__ char smem[];
    int*   s_perm = (int*)smem;                  // [128]
    float* s_bias = (float*)(smem + 512);        // [128]
    char*  a_sm   = smem + SMEM_HDR;
    char*  b_sm   = a_sm + TILE_B;

    int tid  = threadIdx.x;
    int lane = tid & 31;
    int wid  = tid >> 5;
    int wm   = wid & 1;          // 2 warp rows (64 rows each)
    int wn   = wid >> 1;         // 4 warp cols (32 cols each)

    if (tid < 128) {
        int r = m0 + tid;
        s_perm[tid] = (r < cnt) ? g_perm[off + r] : -1;
        s_bias[tid] = b_nei[(size_t)c * E_ + nt * NT + tid];
    }

    // load A tile: 128 rows x 18 x 16B chunks (zero-fill past cnt)
    const char* Ag = (const char*)g_Ab + (size_t)(off + m0) * ROWB_;
#pragma unroll
    for (int it = 0; it < 9; it++) {
        int idx = it * 256 + tid;
        int r = idx / 18, ch = idx % 18;
        uint4 v = make_uint4(0, 0, 0, 0);
        if (m0 + r < cnt) v = *(const uint4*)(Ag + (size_t)r * ROWB_ + ch * 16);
        *(uint4*)(a_sm + r * STRIDE_B + ch * 16) = v;
    }
    // load B tile: 128 weight rows (output cols nt*128..+128)
    const char* Bg = (const char*)g_Wb + ((size_t)c * E_ + nt * NT) * ROWB_;
#pragma unroll
    for (int it = 0; it < 9; it++) {
        int idx = it * 256 + tid;
        int r = idx / 18, ch = idx % 18;
        uint4 v = *(const uint4*)(Bg + (size_t)r * ROWB_ + ch * 16);
        *(uint4*)(b_sm + r * STRIDE_B + ch * 16) = v;
    }
    __syncthreads();

    // ldmatrix lane address bases
    uint32_t a_u32 = smem_u32(a_sm);
    uint32_t b_u32 = smem_u32(b_sm);
    // A x4: lanes 0-15 -> rows m, k0; lanes 16-31 -> rows m, k0+8
    uint32_t a_base = a_u32 + (uint32_t)(wm * 64 + (lane & 15)) * STRIDE_B
                            + ((lane >> 4) << 4);
    // B x4: matrices (n0 k0), (n0 k8), (n0+8 k0), (n0+8 k8)
    uint32_t b_base = b_u32 + (uint32_t)(wn * 32 + ((lane >> 4) << 3) + (lane & 7)) * STRIDE_B
                            + (((lane >> 3) & 1) << 4);

    float acc[4][4][4];
#pragma unroll
    for (int i = 0; i < 4; i++)
#pragma unroll
        for (int j = 0; j < 4; j++)
#pragma unroll
            for (int q = 0; q < 4; q++) acc[i][j][q] = 0.f;

#pragma unroll
    for (int kc = 0; kc < 9; kc++) {           // K' = 144 = 9 x 16
        uint32_t kb = kc * 32;                 // k0 * 2 bytes
        uint32_t B0[4], B1[4];
        ldsm_x4(B0[0], B0[1], B0[2], B0[3], b_base + kb);              // ntiles 0,1
        ldsm_x4(B1[0], B1[1], B1[2], B1[3], b_base + 16 * STRIDE_B + kb); // ntiles 2,3
#pragma unroll
        for (int mi = 0; mi < 4; mi++) {
            uint32_t A[4];
            ldsm_x4(A[0], A[1], A[2], A[3], a_base + (uint32_t)mi * 16 * STRIDE_B + kb);
            mma16816(acc[mi][0], A, B0[0], B0[1]);
            mma16816(acc[mi][1], A, B0[2], B0[3]);
            mma16816(acc[mi][2], A, B1[0], B1[1]);
            mma16816(acc[mi][3], A, B1[2], B1[3]);
        }
    }

    // epilogue: c0,c1 -> row g cols t*2,+1 ; c2,c3 -> row g+8
    int g = lane >> 2, t4 = lane & 3;
#pragma unroll
    for (int mi = 0; mi < 4; mi++) {
#pragma unroll
        for (int half = 0; half < 2; half++) {
            int rloc = wm * 64 + mi * 16 + g + half * 8;
            int rg   = s_perm[rloc];
            if (rg >= 0) {
                float* orow = out_nei + (size_t)rg * E_ + nt * NT + wn * 32;
#pragma unroll
                for (int ni = 0; ni < 4; ni++) {
                    int colo = ni * 8 + t4 * 2;
                    float2 v = make_float2(
                        acc[mi][ni][half * 2 + 0] + s_bias[wn * 32 + colo],
                        acc[mi][ni][half * 2 + 1] + s_bias[wn * 32 + colo + 1]);
                    *(float2*)(orow + colo) = v;
                }
            }
        }
    }
}

// ---------------- kernel 5: anchor ----------------
__global__ void k_anchor(const float* __restrict__ init_trajs,
                         const float* __restrict__ W_self,
                         const float* __restrict__ b_self) {
    int c  = blockIdx.x / K_;
    int kk = blockIdx.x % K_;
    __shared__ float tr[PRED_ * IN_];
    if (threadIdx.x < PRED_ * IN_)
        tr[threadIdx.x] = init_trajs[((size_t)c * K_ + kk) * (PRED_ * IN_) + threadIdx.x];
    __syncthreads();

    int col = threadIdx.x * 4;
    const float* bb = b_self + (size_t)c * E_ + col;
    float4 acc = *(const float4*)bb;
    const float* W = W_self + ((size_t)c * DSELF_ + DNEI_) * E_ + col;
#pragma unroll 8
    for (int j = 0; j < PRED_ * IN_; j++) {
        float  t = tr[j];
        float4 w = *(const float4*)(W + (size_t)j * E_);
        acc.x += t * w.x; acc.y += t * w.y; acc.z += t * w.z; acc.w += t * w.w;
    }
    *(float4*)(g_anchor + ((size_t)c * K_ + kk) * E_ + col) = acc;
}

// ---------------- kernel 6: x path ----------------
__global__ void k_x(const float* __restrict__ obs,
                    const float* __restrict__ W_self,
                    const int*   __restrict__ self_labels,
                    float*       __restrict__ out_x) {
    int b = blockIdx.x;
    __shared__ float ob[DNEI_];
    if (threadIdx.x < DNEI_)
        ob[threadIdx.x] = obs[(size_t)b * DNEI_ + threadIdx.x];
    __syncthreads();

    int c   = self_labels[b];
    int col = threadIdx.x * 4;
    const float* W = W_self + (size_t)c * DSELF_ * E_ + col;
    float4 acc = make_float4(0.f, 0.f, 0.f, 0.f);
#pragma unroll 8
    for (int j = 0; j < DNEI_; j++) {
        float  t = ob[j];
        float4 w = *(const float4*)(W + (size_t)j * E_);
        acc.x += t * w.x; acc.y += t * w.y; acc.z += t * w.z; acc.w += t * w.w;
    }
#pragma unroll
    for (int kk = 0; kk < K_; kk++) {
        float4 an = *(const float4*)(g_anchor + ((size_t)c * K_ + kk) * E_ + col);
        float4 v  = make_float4(acc.x + an.x, acc.y + an.y, acc.z + an.z, acc.w + an.w);
        *(float4*)(out_x + ((size_t)b * K_ + kk) * E_ + col) = v;
    }
}

// ---------------- launcher ----------------
extern "C" void kernel_launch(void* const* d_in, const int* in_sizes, int n_in,
                              void* d_out, int out_size) {
    const float* obs         = (const float*)d_in[0];
    const float* neis        = (const float*)d_in[1];
    const float* init_trajs  = (const float*)d_in[2];
    const float* W_self      = (const float*)d_in[3];
    const float* b_self      = (const float*)d_in[4];
    const float* W_nei       = (const float*)d_in[5];
    const float* b_nei       = (const float*)d_in[6];
    const int*   self_labels = (const int*)d_in[7];
    const int*   nei_labels  = (const int*)d_in[8];

    float* out_x   = (float*)d_out;
    float* out_nei = (float*)d_out + X_ELEMS;

    static int s_attr_done = 0;
    if (!s_attr_done) {
        cudaFuncSetAttribute(k_gemm_mma, cudaFuncAttributeMaxDynamicSharedMemorySize, SMEM_BYTES);
        s_attr_done = 1;
    }

    // nei_feats path
    k_wprep<<<(CN_ * E_ + 255) / 256, 256>>>(W_nei);
    k_count<<<NBLK_, 256>>>(nei_labels);
    k_prefix<<<1, 256>>>();
    k_scattercopy<<<NBLK_, 256>>>(neis, nei_labels);
    k_gemm_mma<<<GEMM_GRID, 256, SMEM_BYTES>>>(b_nei, out_nei);

    // x path
    k_anchor<<<C_ * K_, 128>>>(init_trajs, W_self, b_self);
    k_x<<<B_, 128>>>(obs, W_self, self_labels, out_x);
}